// round 13
// baseline (speedup 1.0000x reference)
#include <cuda_runtime.h>
#include <cuda_bf16.h>
#include <cstdint>

#define NB   64      // batch
#define TT   64      // seq len
#define NN   1024    // items
#define SS   32      // state dim
#define DD   32      // item dim
#define FF   64      // feature = SS + DD
#define GG   96      // 3 * SS
#define MAXDEG 96
#define CSCPAD 112   // padded stride so unroll-16 gather never reads OOB
#define BN   (NB * NN)

// Persistent state (module globals — no runtime allocation)
__device__ float g_h[BN * SS];          // (row, s) row-major
__device__ float g_Gi[GG * BN];         // TRANSPOSED: (g, row)
__device__ int   g_csc[NN * CSCPAD];    // in-neighbors of each v (zero-padded)
__device__ int   g_deg[NN];
__device__ float g_Cn[NN * DD];         // adj^T @ item_emb
// Folded weights
__device__ float g_M[192 * 128];        // [w_ih@w_in ; w_ih@w_out], original order
__device__ float g_MX_T[64 * 192];      // transposed, permuted-g: cols {h, agg}
__device__ float g_MCr[384 * 32];       // row-major: rows 0-191 qS weights, 192-383 qX
__device__ float g_Pc[NN * 192];        // per-node constant (permuted-g) incl. bias fold
__device__ float g_Q[(size_t)NB * TT * 384];  // precomputed qS|qX per (b,t)

__device__ __forceinline__ float sigmf(float x) {
    return 1.0f / (1.0f + __expf(-x));
}
__device__ __forceinline__ float tanhfast(float x) {
    float e = __expf(-2.0f * x);
    return (1.0f - e) / (1.0f + e);
}

// permuted g position: [in 0:48 | out 0:48 | in 48:96 | out 48:96]
__device__ __forceinline__ int gpos(int gg, int is_out) {
    return (gg / 48) * 96 + (is_out ? 48 : 0) + (gg % 48);
}

// ---------------------------------------------------------------------------
// Build CSC (zero-padded to CSCPAD)
// ---------------------------------------------------------------------------
__global__ void build_csc_kernel(const float* __restrict__ adj) {
    int v = blockIdx.x;
    int t = threadIdx.x;          // 256 threads, each handles 4 u's
    __shared__ int cnt[256];

    int base = t * 4;
    int flags = 0, c = 0;
    #pragma unroll
    for (int i = 0; i < 4; i++) {
        float a = adj[(base + i) * NN + v];
        if (a != 0.0f) { c++; flags |= (1 << i); }
    }
    cnt[t] = c;
    __syncthreads();
    for (int st = 1; st < 256; st <<= 1) {
        int val = cnt[t];
        int add = (t >= st) ? cnt[t - st] : 0;
        __syncthreads();
        cnt[t] = val + add;
        __syncthreads();
    }
    int off = cnt[t] - c;
    int total = cnt[255];
    int w = 0;
    #pragma unroll
    for (int i = 0; i < 4; i++) {
        if (flags & (1 << i)) {
            int idx = off + w;
            if (idx < MAXDEG) g_csc[v * CSCPAD + idx] = base + i;
            w++;
        }
    }
    int tot = (total < MAXDEG) ? total : MAXDEG;
    if (t == 0) g_deg[v] = tot;
    for (int p = tot + t; p < CSCPAD; p += 256) g_csc[v * CSCPAD + p] = 0;
}

__global__ void build_cn_kernel(const float* __restrict__ item_emb) {
    int v = blockIdx.x;
    int d = threadIdx.x;
    int deg = g_deg[v];
    float s = 0.0f;
    for (int k = 0; k < deg; k++) {
        int u = g_csc[v * CSCPAD + k];
        s += item_emb[u * DD + d];
    }
    g_Cn[v * DD + d] = s;
}

// ---------------------------------------------------------------------------
// M = [w_ih @ w_in ; w_ih @ w_out]  (192 x 128) + transposed/permuted slices
// ---------------------------------------------------------------------------
__global__ void build_M_kernel(const float* __restrict__ w_ih,
                               const float* __restrict__ w_in,
                               const float* __restrict__ w_out) {
    int idx = blockIdx.x;          // 0..191
    int k = threadIdx.x;           // 0..127
    int is_out = idx >= 96;
    int gg = idx % 96;
    int pos = gpos(gg, is_out);
    const float* wio = is_out ? w_out : w_in;
    float acc = 0.0f;
    #pragma unroll 8
    for (int o = 0; o < FF; o++) acc += w_ih[gg * FF + o] * wio[o * 128 + k];
    g_M[idx * 128 + k] = acc;
    if (k < 32)                 g_MX_T[k * 192 + pos] = acc;            // h cols
    else if (k >= 64 && k < 96) g_MX_T[(k - 32) * 192 + pos] = acc;     // agg cols
    else if (k >= 32 && k < 64) g_MCr[pos * 32 + (k - 32)] = acc;       // merged (qS)
    else                        g_MCr[(192 + pos) * 32 + (k - 96)] = acc; // Cn (qX)
}

// Pc[v][pos] = M[:,32:64]@item_emb[v] + M[:,96:128]@Cn[v] + w_ih@bias
__global__ void __launch_bounds__(192) build_Pc_kernel(
    const float* __restrict__ item_emb,
    const float* __restrict__ w_ih,
    const float* __restrict__ b_in,
    const float* __restrict__ b_out) {
    int idx = threadIdx.x;   // 0..191
    int is_out = idx >= 96;
    int gg = idx % 96;
    int pos = gpos(gg, is_out);

    __shared__ float ie[16][32];
    __shared__ float cn[16][32];
    int v0 = blockIdx.x * 16;
    for (int i = idx; i < 16 * 32; i += 192) {
        int vv = i >> 5, d = i & 31;
        ie[vv][d] = item_emb[(v0 + vv) * DD + d];
        cn[vv][d] = g_Cn[(v0 + vv) * DD + d];
    }

    float m1[32], m2[32];
    #pragma unroll
    for (int k = 0; k < 32; k++) {
        m1[k] = g_M[idx * 128 + 32 + k];
        m2[k] = g_M[idx * 128 + 96 + k];
    }
    const float* bio = is_out ? b_out : b_in;
    float wb = 0.0f;
    #pragma unroll 8
    for (int o = 0; o < FF; o++) wb += w_ih[gg * FF + o] * bio[o];
    __syncthreads();

    for (int vv = 0; vv < 16; vv++) {
        float acc = wb;
        #pragma unroll
        for (int k = 0; k < 32; k++)
            acc += m1[k] * ie[vv][k] + m2[k] * cn[vv][k];
        g_Pc[(v0 + vv) * 192 + pos] = acc;
    }
}

// ---------------------------------------------------------------------------
// Q table: for every (b, t) precompute qS(192) | qX(192).
// grid (TT, NB) x 384; thread reads its contiguous 32-float g_MCr row.
// ---------------------------------------------------------------------------
__global__ void __launch_bounds__(384) build_Q_kernel(
    const int* __restrict__ item_ids, const int* __restrict__ responses,
    const float* __restrict__ item_emb, const float* __restrict__ resp_emb) {
    int t = blockIdx.x, b = blockIdx.y;
    int idx = threadIdx.x;           // 0..383
    __shared__ float sd[32];
    if (idx < 32) {
        int item = item_ids[b * TT + t];
        int resp = responses[b * TT + t];
        sd[idx] = resp_emb[resp * DD + idx] - item_emb[item * DD + idx];
    }
    __syncthreads();
    const float4* row = reinterpret_cast<const float4*>(g_MCr + idx * 32);
    float acc = 0.0f;
    #pragma unroll
    for (int q = 0; q < 8; q++) {
        float4 wv = row[q];
        acc += wv.x * sd[q * 4 + 0] + wv.y * sd[q * 4 + 1]
             + wv.z * sd[q * 4 + 2] + wv.w * sd[q * 4 + 3];
    }
    g_Q[((size_t)b * TT + t) * 384 + idx] = acc;
}

__global__ void init_state_kernel(const float* __restrict__ b_ih) {
    int i = blockIdx.x * blockDim.x + threadIdx.x;
    if (i < GG * BN) g_Gi[i] = b_ih[i / BN];
    if (i < BN * SS) g_h[i] = 0.0f;
}

// ---------------------------------------------------------------------------
// Kernel A4: sparse Gi refresh, fused halves, precomputed Q.
// Grid: NB blocks x 512 threads (16 warps); warp-per-node.
// Dynamic shared layout (floats):
//   [0)         MXs   64*192 = 12288
//   [12288)     tbuf  16*192 = 3072
//   [15360)     xbuf  16*64  = 1024
//   [16384)     qS 192 | qX 192 | bihs 96   (=480)
// total 16864 floats = 67456 bytes
// ---------------------------------------------------------------------------
#define SP4_SMEM_FLOATS 16864
#define SP4_SMEM_BYTES  (SP4_SMEM_FLOATS * 4)

__global__ void __launch_bounds__(512) step_sparse4(
    const int* __restrict__ item_ids, int t,
    const float* __restrict__ adj,
    const float* __restrict__ in_a, const float* __restrict__ out_a,
    const float* __restrict__ b_ih)
{
    extern __shared__ float smem[];
    float* MXs   = smem;                 // [64][192]
    float* tbufA = smem + 12288;         // [16][192]
    float* xbufA = smem + 15360;         // [16][64]
    float* qS    = smem + 16384;         // [192]
    float* qX    = qS + 192;             // [192]
    float* bihs  = qX + 192;             // [96]

    int b = blockIdx.x;
    int tid = threadIdx.x, lane = tid & 31, w = tid >> 5;
    int item = item_ids[b * TT + t];
    int deg = g_deg[item];

    // prologue: weights + small vectors (all coalesced)
    for (int i = tid; i < 64 * 192; i += 512) MXs[i] = g_MX_T[i];
    if (tid < 384) qS[tid] = g_Q[((size_t)b * TT + t) * 384 + tid];
    if (tid >= 384 && tid < 480) bihs[tid - 384] = b_ih[tid - 384];
    __syncthreads();

    const float* hb = g_h + (size_t)b * NN * SS;
    float* xb = xbufA + w * 64;
    float* tb = tbufA + w * 192;

    for (int j = w; j < deg; j += 16) {
        int v = g_csc[item * CSCPAD + j];

        // ---- gather agg: 16 loads in flight, 2 accumulator chains ----
        int degv = g_deg[v];
        const int* nb = g_csc + v * CSCPAD;
        float acc0 = 0.0f, acc1 = 0.0f;
        for (int k = 0; k < degv; k += 16) {
            #pragma unroll
            for (int i = 0; i < 16; i += 2) {
                int u0 = nb[k + i];
                int u1 = nb[k + i + 1];
                float x0 = hb[u0 * SS + lane];
                float x1 = hb[u1 * SS + lane];
                if (k + i < degv)     acc0 += x0;
                if (k + i + 1 < degv) acc1 += x1;
            }
        }
        float hv = hb[v * SS + lane];
        xb[lane] = hv;
        xb[32 + lane] = acc0 + acc1;
        __syncwarp();

        // ---- 192x64 matvec: lane owns 6 outputs (pos = lane + 32m) ----
        bool hasrev = adj[(size_t)item * NN + v] != 0.0f;
        bool isself = (v == item);
        float acc[6];
        #pragma unroll
        for (int m = 0; m < 6; m++) {
            int pos = lane + 32 * m;
            float a = g_Pc[v * 192 + pos];
            if (hasrev) a += qX[pos];
            if (isself) a += qS[pos];
            acc[m] = a;
        }
        #pragma unroll
        for (int k = 0; k < 64; k++) {
            float xk = xb[k];
            #pragma unroll
            for (int m = 0; m < 6; m++)
                acc[m] += MXs[k * 192 + lane + 32 * m] * xk;
        }
        #pragma unroll
        for (int m = 0; m < 6; m++) tb[lane + 32 * m] = acc[m];
        __syncwarp();

        // ---- epilogue: Gi[gg] = b_ih + in_a*t_in + out_a*t_out ----
        float ia = in_a[v], oa = out_a[v];
        #pragma unroll
        for (int m = 0; m < 3; m++) {
            int gg = lane + 32 * m;
            int q = (gg >= 48) ? 1 : 0;
            int pos_in = q * 96 + (gg - 48 * q);
            float gi = bihs[gg] + ia * tb[pos_in] + oa * tb[pos_in + 48];
            g_Gi[(size_t)gg * BN + b * NN + v] = gi;
        }
        __syncwarp();
    }
}

// ---------------------------------------------------------------------------
// Kernel B4: GRU, one row per thread, float4 shared weight loads, fully
// unrolled, low register pressure. grid 256 x 256.
// ---------------------------------------------------------------------------
__global__ void __launch_bounds__(256) step_gru4(
    const float* __restrict__ w_hh, const float* __restrict__ b_hh,
    const float* __restrict__ w_fc, const float* __restrict__ b_fc,
    float* __restrict__ out, int t, float* __restrict__ h_final)
{
    __shared__ __align__(16) float whh[GG * SS];
    __shared__ float bhh[GG];
    __shared__ float wfc[SS];

    int tid = threadIdx.x;
    for (int i = tid; i < GG * SS; i += 256) whh[i] = w_hh[i];
    if (tid < GG) bhh[tid] = b_hh[tid];
    if (tid < SS) wfc[tid] = w_fc[tid];
    __syncthreads();

    const float4* whh4 = reinterpret_cast<const float4*>(whh);

    int r = blockIdx.x * 256 + tid;

    float h[SS];
    {
        const float4* hp = reinterpret_cast<const float4*>(g_h + (size_t)r * SS);
        #pragma unroll
        for (int q = 0; q < 8; q++) {
            float4 hv = hp[q];
            h[q * 4 + 0] = hv.x; h[q * 4 + 1] = hv.y;
            h[q * 4 + 2] = hv.z; h[q * 4 + 3] = hv.w;
        }
    }

    float4* hrow  = reinterpret_cast<float4*>(g_h + (size_t)r * SS);
    float4* hfrow = h_final ? reinterpret_cast<float4*>(h_final + (size_t)r * SS)
                            : nullptr;

    float fc = 0.0f;
    float o0, o1, o2, o3;

    #pragma unroll
    for (int d = 0; d < SS; d++) {
        float ar = bhh[d], az = bhh[SS + d], an = bhh[2 * SS + d];
        #pragma unroll
        for (int q = 0; q < 8; q++) {
            float4 wr = whh4[(d * SS) / 4 + q];
            float4 wz = whh4[((SS + d) * SS) / 4 + q];
            float4 wn = whh4[((2 * SS + d) * SS) / 4 + q];
            float h0 = h[q * 4 + 0], h1 = h[q * 4 + 1];
            float h2 = h[q * 4 + 2], h3 = h[q * 4 + 3];
            ar += wr.x * h0 + wr.y * h1 + wr.z * h2 + wr.w * h3;
            az += wz.x * h0 + wz.y * h1 + wz.z * h2 + wz.w * h3;
            an += wn.x * h0 + wn.y * h1 + wn.z * h2 + wn.w * h3;
        }
        float gr = g_Gi[(size_t)d * BN + r];
        float gz = g_Gi[(size_t)(SS + d) * BN + r];
        float gn = g_Gi[(size_t)(2 * SS + d) * BN + r];
        float rr = sigmf(ar + gr);
        float zz = sigmf(az + gz);
        float nn = tanhfast(gn + rr * an);
        float hn = (1.0f - zz) * nn + zz * h[d];
        fc += hn * wfc[d];
        if ((d & 3) == 0) o0 = hn;
        else if ((d & 3) == 1) o1 = hn;
        else if ((d & 3) == 2) o2 = hn;
        else {
            o3 = hn;
            float4 ov; ov.x = o0; ov.y = o1; ov.z = o2; ov.w = o3;
            hrow[d / 4] = ov;
            if (hfrow) hfrow[d / 4] = ov;
        }
    }

    int b0 = r >> 10;
    int v0 = r & (NN - 1);
    out[((size_t)b0 * TT + t) * NN + v0] = sigmf(fc + b_fc[0]);
}

// ---------------------------------------------------------------------------
extern "C" void kernel_launch(void* const* d_in, const int* in_sizes, int n_in,
                              void* d_out, int out_size) {
    const int*   item_ids  = (const int*)  d_in[0];
    const int*   responses = (const int*)  d_in[1];
    const float* adj       = (const float*)d_in[2];
    const float* item_emb  = (const float*)d_in[3];
    const float* resp_emb  = (const float*)d_in[4];
    const float* w_in      = (const float*)d_in[5];
    const float* b_in      = (const float*)d_in[6];
    const float* w_out     = (const float*)d_in[7];
    const float* b_out     = (const float*)d_in[8];
    const float* in_a      = (const float*)d_in[9];
    const float* out_a     = (const float*)d_in[10];
    const float* w_ih      = (const float*)d_in[11];
    const float* w_hh      = (const float*)d_in[12];
    const float* b_ih      = (const float*)d_in[13];
    const float* b_hh      = (const float*)d_in[14];
    const float* w_fc      = (const float*)d_in[15];
    const float* b_fc      = (const float*)d_in[16];

    float* out    = (float*)d_out;                       // (B, T, N)
    float* h_out  = out + (size_t)NB * TT * NN;          // (B, N, S)

    cudaFuncSetAttribute(step_sparse4,
                         cudaFuncAttributeMaxDynamicSharedMemorySize,
                         SP4_SMEM_BYTES);

    build_csc_kernel<<<NN, 256>>>(adj);
    build_cn_kernel<<<NN, 32>>>(item_emb);
    build_M_kernel<<<192, 128>>>(w_ih, w_in, w_out);
    build_Pc_kernel<<<NN / 16, 192>>>(item_emb, w_ih, b_in, b_out);
    build_Q_kernel<<<dim3(TT, NB), 384>>>(item_ids, responses, item_emb, resp_emb);
    {
        int total = GG * BN;
        init_state_kernel<<<(total + 255) / 256, 256>>>(b_ih);
    }

    for (int t = 0; t < TT; t++) {
        step_sparse4<<<NB, 512, SP4_SMEM_BYTES>>>(
            item_ids, t, adj, in_a, out_a, b_ih);
        step_gru4<<<BN / 256, 256>>>(
            w_hh, b_hh, w_fc, b_fc, out, t,
            (t == TT - 1) ? h_out : nullptr);
    }
}

// round 14
// speedup vs baseline: 1.2024x; 1.2024x over previous
#include <cuda_runtime.h>
#include <cuda_bf16.h>
#include <cstdint>

#define NB   64      // batch
#define TT   64      // seq len
#define NN   1024    // items
#define SS   32      // state dim
#define DD   32      // item dim
#define FF   64      // feature = SS + DD
#define GG   96      // 3 * SS
#define MAXDEG 96
#define CSCPAD 112   // padded stride so unroll-16 gather never reads OOB
#define BN   (NB * NN)

// Persistent state (module globals — no runtime allocation)
__device__ float g_h[BN * SS];          // (row, s) row-major
__device__ float g_Gi[GG * BN];         // TRANSPOSED: (g, row)
__device__ int   g_csc[NN * CSCPAD];    // in-neighbors of each v (zero-padded)
__device__ int   g_deg[NN];
__device__ float g_Cn[NN * DD];         // adj^T @ item_emb
// Folded weights
__device__ float g_M[192 * 128];        // [w_ih@w_in ; w_ih@w_out], original order
__device__ float g_MX_T[64 * 192];      // transposed, permuted-g: cols {h, agg}
__device__ float g_MCr[384 * 32];       // row-major: rows 0-191 qS weights, 192-383 qX
__device__ float g_Pc[NN * 192];        // per-node constant (permuted-g) incl. bias fold
__device__ float g_Q[(size_t)NB * TT * 384];  // precomputed qS|qX per (b,t)

__device__ __forceinline__ float sigmf(float x) {
    return 1.0f / (1.0f + __expf(-x));
}
__device__ __forceinline__ float tanhfast(float x) {
    float e = __expf(-2.0f * x);
    return (1.0f - e) / (1.0f + e);
}

// permuted g position: [in 0:48 | out 0:48 | in 48:96 | out 48:96]
__device__ __forceinline__ int gpos(int gg, int is_out) {
    return (gg / 48) * 96 + (is_out ? 48 : 0) + (gg % 48);
}

// ---------------------------------------------------------------------------
// Setup launch 1: build CSC (zero-padded to CSCPAD)
// ---------------------------------------------------------------------------
__global__ void build_csc_kernel(const float* __restrict__ adj) {
    int v = blockIdx.x;
    int t = threadIdx.x;          // 256 threads, each handles 4 u's
    __shared__ int cnt[256];

    int base = t * 4;
    int flags = 0, c = 0;
    #pragma unroll
    for (int i = 0; i < 4; i++) {
        float a = adj[(base + i) * NN + v];
        if (a != 0.0f) { c++; flags |= (1 << i); }
    }
    cnt[t] = c;
    __syncthreads();
    for (int st = 1; st < 256; st <<= 1) {
        int val = cnt[t];
        int add = (t >= st) ? cnt[t - st] : 0;
        __syncthreads();
        cnt[t] = val + add;
        __syncthreads();
    }
    int off = cnt[t] - c;
    int total = cnt[255];
    int w = 0;
    #pragma unroll
    for (int i = 0; i < 4; i++) {
        if (flags & (1 << i)) {
            int idx = off + w;
            if (idx < MAXDEG) g_csc[v * CSCPAD + idx] = base + i;
            w++;
        }
    }
    int tot = (total < MAXDEG) ? total : MAXDEG;
    if (t == 0) g_deg[v] = tot;
    for (int p = tot + t; p < CSCPAD; p += 256) g_csc[v * CSCPAD + p] = 0;
}

// ---------------------------------------------------------------------------
// Setup launch 2 (merged): blocks 0-255 -> Cn (4 nodes each);
//                          blocks 256-447 -> M row (idx = blockIdx-256)
// ---------------------------------------------------------------------------
__global__ void setup2_kernel(const float* __restrict__ item_emb,
                              const float* __restrict__ w_ih,
                              const float* __restrict__ w_in,
                              const float* __restrict__ w_out) {
    if (blockIdx.x < 256) {
        // Cn[v][d] = sum over in-neighbors u of item_emb[u][d]
        int v = blockIdx.x * 4 + (threadIdx.x >> 5);
        int d = threadIdx.x & 31;
        int deg = g_deg[v];
        float s = 0.0f;
        for (int k = 0; k < deg; k++) {
            int u = g_csc[v * CSCPAD + k];
            s += item_emb[u * DD + d];
        }
        g_Cn[v * DD + d] = s;
    } else {
        int idx = blockIdx.x - 256;    // 0..191
        int k = threadIdx.x;           // 0..127
        int is_out = idx >= 96;
        int gg = idx % 96;
        int pos = gpos(gg, is_out);
        const float* wio = is_out ? w_out : w_in;
        float acc = 0.0f;
        #pragma unroll 8
        for (int o = 0; o < FF; o++) acc += w_ih[gg * FF + o] * wio[o * 128 + k];
        g_M[idx * 128 + k] = acc;
        if (k < 32)                 g_MX_T[k * 192 + pos] = acc;            // h cols
        else if (k >= 64 && k < 96) g_MX_T[(k - 32) * 192 + pos] = acc;     // agg cols
        else if (k >= 32 && k < 64) g_MCr[pos * 32 + (k - 32)] = acc;       // merged (qS)
        else                        g_MCr[(192 + pos) * 32 + (k - 96)] = acc; // Cn (qX)
    }
}

// ---------------------------------------------------------------------------
// Setup launch 3 (merged): blocks 0-63 -> Pc (16 nodes each);
//   blocks 64-4159 -> Q table per (b,t); blocks 4160-20543 -> state init.
// ---------------------------------------------------------------------------
#define S3_PC_BLOCKS 64
#define S3_Q_BLOCKS  (NB * TT)
#define S3_INIT_BLOCKS ((GG * BN) / 384)
#define S3_GRID (S3_PC_BLOCKS + S3_Q_BLOCKS + S3_INIT_BLOCKS)

__global__ void __launch_bounds__(384) setup3_kernel(
    const int* __restrict__ item_ids, const int* __restrict__ responses,
    const float* __restrict__ item_emb, const float* __restrict__ resp_emb,
    const float* __restrict__ w_ih,
    const float* __restrict__ b_in, const float* __restrict__ b_out,
    const float* __restrict__ b_ih) {
    __shared__ float sbuf[16 * 32 * 2];   // Pc: ie|cn ; Q: sd (first 32)
    int bx = blockIdx.x;
    int tid = threadIdx.x;

    if (bx < S3_PC_BLOCKS) {
        // ---- build_Pc: 16 nodes, threads 0-191 active ----
        float* ie = sbuf;            // [16][32]
        float* cn = sbuf + 512;      // [16][32]
        int v0 = bx * 16;
        for (int i = tid; i < 16 * 32; i += 384) {
            int vv = i >> 5, d = i & 31;
            ie[vv * 32 + d] = item_emb[(v0 + vv) * DD + d];
            cn[vv * 32 + d] = g_Cn[(v0 + vv) * DD + d];
        }
        __syncthreads();
        if (tid < 192) {
            int idx = tid;
            int is_out = idx >= 96;
            int gg = idx % 96;
            int pos = gpos(gg, is_out);
            float m1[32], m2[32];
            #pragma unroll
            for (int k = 0; k < 32; k++) {
                m1[k] = g_M[idx * 128 + 32 + k];
                m2[k] = g_M[idx * 128 + 96 + k];
            }
            const float* bio = is_out ? b_out : b_in;
            float wb = 0.0f;
            #pragma unroll 8
            for (int o = 0; o < FF; o++) wb += w_ih[gg * FF + o] * bio[o];
            for (int vv = 0; vv < 16; vv++) {
                float acc = wb;
                #pragma unroll
                for (int k = 0; k < 32; k++)
                    acc += m1[k] * ie[vv * 32 + k] + m2[k] * cn[vv * 32 + k];
                g_Pc[(v0 + vv) * 192 + pos] = acc;
            }
        }
    } else if (bx < S3_PC_BLOCKS + S3_Q_BLOCKS) {
        // ---- build_Q for one (b, t) ----
        int idx2 = bx - S3_PC_BLOCKS;
        int t = idx2 % TT, b = idx2 / TT;
        float* sd = sbuf;
        if (tid < 32) {
            int item = item_ids[b * TT + t];
            int resp = responses[b * TT + t];
            sd[tid] = resp_emb[resp * DD + tid] - item_emb[item * DD + tid];
        }
        __syncthreads();
        const float4* row = reinterpret_cast<const float4*>(g_MCr + tid * 32);
        float acc = 0.0f;
        #pragma unroll
        for (int q = 0; q < 8; q++) {
            float4 wv = row[q];
            acc += wv.x * sd[q * 4 + 0] + wv.y * sd[q * 4 + 1]
                 + wv.z * sd[q * 4 + 2] + wv.w * sd[q * 4 + 3];
        }
        g_Q[((size_t)b * TT + t) * 384 + tid] = acc;
    } else {
        // ---- init state ----
        int i = (bx - S3_PC_BLOCKS - S3_Q_BLOCKS) * 384 + tid;
        g_Gi[i] = b_ih[i / BN];
        if (i < BN * SS) g_h[i] = 0.0f;
    }
}

// ---------------------------------------------------------------------------
// Kernel A5: sparse Gi refresh. Grid (2, NB) x 512 threads; 32 warps per
// batch share the ~33 nodes (j = half*16 + w, stride 32).
// Dynamic shared (floats): MXs 12288 | tbuf 16*192 | xbuf 16*64 | q 384 | bihs 96
// ---------------------------------------------------------------------------
#define SP5_SMEM_FLOATS (12288 + 3072 + 1024 + 384 + 96)
#define SP5_SMEM_BYTES  (SP5_SMEM_FLOATS * 4)

__global__ void __launch_bounds__(512) step_sparse5(
    const int* __restrict__ item_ids, int t,
    const float* __restrict__ adj,
    const float* __restrict__ in_a, const float* __restrict__ out_a,
    const float* __restrict__ b_ih)
{
    extern __shared__ float smem[];
    float* MXs   = smem;                 // [64][192]
    float* tbufA = smem + 12288;         // [16][192]
    float* xbufA = smem + 15360;         // [16][64]
    float* qS    = smem + 16384;         // [192]
    float* qX    = qS + 192;             // [192]
    float* bihs  = qX + 192;             // [96]

    int b = blockIdx.y, half = blockIdx.x;
    int tid = threadIdx.x, lane = tid & 31, w = tid >> 5;
    int item = item_ids[b * TT + t];
    int deg = g_deg[item];

    // prologue: weights + small vectors (all coalesced)
    for (int i = tid; i < 64 * 192; i += 512) MXs[i] = g_MX_T[i];
    if (tid < 384) qS[tid] = g_Q[((size_t)b * TT + t) * 384 + tid];
    if (tid >= 384 && tid < 480) bihs[tid - 384] = b_ih[tid - 384];
    __syncthreads();

    const float* hb = g_h + (size_t)b * NN * SS;
    float* xb = xbufA + w * 64;
    float* tb = tbufA + w * 192;

    for (int j = half * 16 + w; j < deg; j += 32) {
        int v = g_csc[item * CSCPAD + j];

        // ---- gather agg: 16 loads in flight, 2 accumulator chains ----
        int degv = g_deg[v];
        const int* nb = g_csc + v * CSCPAD;
        float acc0 = 0.0f, acc1 = 0.0f;
        for (int k = 0; k < degv; k += 16) {
            #pragma unroll
            for (int i = 0; i < 16; i += 2) {
                int u0 = nb[k + i];
                int u1 = nb[k + i + 1];
                float x0 = hb[u0 * SS + lane];
                float x1 = hb[u1 * SS + lane];
                if (k + i < degv)     acc0 += x0;
                if (k + i + 1 < degv) acc1 += x1;
            }
        }
        float hv = hb[v * SS + lane];
        xb[lane] = hv;
        xb[32 + lane] = acc0 + acc1;
        __syncwarp();

        // ---- 192x64 matvec: lane owns 6 outputs (pos = lane + 32m) ----
        bool hasrev = adj[(size_t)item * NN + v] != 0.0f;
        bool isself = (v == item);
        float acc[6];
        #pragma unroll
        for (int m = 0; m < 6; m++) {
            int pos = lane + 32 * m;
            float a = g_Pc[v * 192 + pos];
            if (hasrev) a += qX[pos];
            if (isself) a += qS[pos];
            acc[m] = a;
        }
        #pragma unroll
        for (int k = 0; k < 64; k++) {
            float xk = xb[k];
            #pragma unroll
            for (int m = 0; m < 6; m++)
                acc[m] += MXs[k * 192 + lane + 32 * m] * xk;
        }
        #pragma unroll
        for (int m = 0; m < 6; m++) tb[lane + 32 * m] = acc[m];
        __syncwarp();

        // ---- epilogue: Gi[gg] = b_ih + in_a*t_in + out_a*t_out ----
        float ia = in_a[v], oa = out_a[v];
        #pragma unroll
        for (int m = 0; m < 3; m++) {
            int gg = lane + 32 * m;
            int q = (gg >= 48) ? 1 : 0;
            int pos_in = q * 96 + (gg - 48 * q);
            float gi = bihs[gg] + ia * tb[pos_in] + oa * tb[pos_in + 48];
            g_Gi[(size_t)gg * BN + b * NN + v] = gi;
        }
        __syncwarp();
    }
}

// ---------------------------------------------------------------------------
// Kernel B5: GRU, one row per thread. Grid 128 x 512 — single balanced wave.
// ---------------------------------------------------------------------------
__global__ void __launch_bounds__(512) step_gru5(
    const float* __restrict__ w_hh, const float* __restrict__ b_hh,
    const float* __restrict__ w_fc, const float* __restrict__ b_fc,
    float* __restrict__ out, int t, float* __restrict__ h_final)
{
    __shared__ __align__(16) float whh[GG * SS];
    __shared__ float bhh[GG];
    __shared__ float wfc[SS];

    int tid = threadIdx.x;
    for (int i = tid; i < GG * SS; i += 512) whh[i] = w_hh[i];
    if (tid < GG) bhh[tid] = b_hh[tid];
    if (tid < SS) wfc[tid] = w_fc[tid];
    __syncthreads();

    const float4* whh4 = reinterpret_cast<const float4*>(whh);

    int r = blockIdx.x * 512 + tid;

    float h[SS];
    {
        const float4* hp = reinterpret_cast<const float4*>(g_h + (size_t)r * SS);
        #pragma unroll
        for (int q = 0; q < 8; q++) {
            float4 hv = hp[q];
            h[q * 4 + 0] = hv.x; h[q * 4 + 1] = hv.y;
            h[q * 4 + 2] = hv.z; h[q * 4 + 3] = hv.w;
        }
    }

    float4* hrow  = reinterpret_cast<float4*>(g_h + (size_t)r * SS);
    float4* hfrow = h_final ? reinterpret_cast<float4*>(h_final + (size_t)r * SS)
                            : nullptr;

    float fc = 0.0f;
    float o0, o1, o2, o3;

    #pragma unroll
    for (int d = 0; d < SS; d++) {
        float ar = bhh[d], az = bhh[SS + d], an = bhh[2 * SS + d];
        #pragma unroll
        for (int q = 0; q < 8; q++) {
            float4 wr = whh4[(d * SS) / 4 + q];
            float4 wz = whh4[((SS + d) * SS) / 4 + q];
            float4 wn = whh4[((2 * SS + d) * SS) / 4 + q];
            float h0 = h[q * 4 + 0], h1 = h[q * 4 + 1];
            float h2 = h[q * 4 + 2], h3 = h[q * 4 + 3];
            ar += wr.x * h0 + wr.y * h1 + wr.z * h2 + wr.w * h3;
            az += wz.x * h0 + wz.y * h1 + wz.z * h2 + wz.w * h3;
            an += wn.x * h0 + wn.y * h1 + wn.z * h2 + wn.w * h3;
        }
        float gr = g_Gi[(size_t)d * BN + r];
        float gz = g_Gi[(size_t)(SS + d) * BN + r];
        float gn = g_Gi[(size_t)(2 * SS + d) * BN + r];
        float rr = sigmf(ar + gr);
        float zz = sigmf(az + gz);
        float nn = tanhfast(gn + rr * an);
        float hn = (1.0f - zz) * nn + zz * h[d];
        fc += hn * wfc[d];
        if ((d & 3) == 0) o0 = hn;
        else if ((d & 3) == 1) o1 = hn;
        else if ((d & 3) == 2) o2 = hn;
        else {
            o3 = hn;
            float4 ov; ov.x = o0; ov.y = o1; ov.z = o2; ov.w = o3;
            hrow[d / 4] = ov;
            if (hfrow) hfrow[d / 4] = ov;
        }
    }

    int b0 = r >> 10;
    int v0 = r & (NN - 1);
    out[((size_t)b0 * TT + t) * NN + v0] = sigmf(fc + b_fc[0]);
}

// ---------------------------------------------------------------------------
extern "C" void kernel_launch(void* const* d_in, const int* in_sizes, int n_in,
                              void* d_out, int out_size) {
    const int*   item_ids  = (const int*)  d_in[0];
    const int*   responses = (const int*)  d_in[1];
    const float* adj       = (const float*)d_in[2];
    const float* item_emb  = (const float*)d_in[3];
    const float* resp_emb  = (const float*)d_in[4];
    const float* w_in      = (const float*)d_in[5];
    const float* b_in      = (const float*)d_in[6];
    const float* w_out     = (const float*)d_in[7];
    const float* b_out     = (const float*)d_in[8];
    const float* in_a      = (const float*)d_in[9];
    const float* out_a     = (const float*)d_in[10];
    const float* w_ih      = (const float*)d_in[11];
    const float* w_hh      = (const float*)d_in[12];
    const float* b_ih      = (const float*)d_in[13];
    const float* b_hh      = (const float*)d_in[14];
    const float* w_fc      = (const float*)d_in[15];
    const float* b_fc      = (const float*)d_in[16];

    float* out    = (float*)d_out;                       // (B, T, N)
    float* h_out  = out + (size_t)NB * TT * NN;          // (B, N, S)

    cudaFuncSetAttribute(step_sparse5,
                         cudaFuncAttributeMaxDynamicSharedMemorySize,
                         SP5_SMEM_BYTES);

    build_csc_kernel<<<NN, 256>>>(adj);
    setup2_kernel<<<448, 128>>>(item_emb, w_ih, w_in, w_out);
    setup3_kernel<<<S3_GRID, 384>>>(item_ids, responses, item_emb, resp_emb,
                                    w_ih, b_in, b_out, b_ih);

    for (int t = 0; t < TT; t++) {
        step_sparse5<<<dim3(2, NB), 512, SP5_SMEM_BYTES>>>(
            item_ids, t, adj, in_a, out_a, b_ih);
        step_gru5<<<BN / 512, 512>>>(
            w_hh, b_hh, w_fc, b_fc, out, t,
            (t == TT - 1) ? h_out : nullptr);
    }
}

// round 16
// speedup vs baseline: 1.3333x; 1.1089x over previous
#include <cuda_runtime.h>
#include <cuda_bf16.h>
#include <cstdint>

#define NB   64      // batch
#define TT   64      // seq len
#define NN   1024    // items
#define SS   32      // state dim
#define DD   32      // item dim
#define FF   64      // feature = SS + DD
#define GG   96      // 3 * SS
#define MAXDEG 96
#define CSCPAD 112   // padded stride so unroll-16 gather never reads OOB
#define BN   (NB * NN)

// Persistent state (module globals — no runtime allocation)
__device__ float g_h[BN * SS];          // (row, s) row-major
__device__ float g_Gi[GG * BN];         // TRANSPOSED: (g, row)
__device__ int   g_csc[NN * CSCPAD];    // in-neighbors of each v (zero-padded)
__device__ int   g_deg[NN];
__device__ float g_Cn[NN * DD];         // adj^T @ item_emb
// Folded weights
__device__ float g_M[192 * 128];        // [w_ih@w_in ; w_ih@w_out], original order
__device__ float g_MXk[192 * 68];       // k-major padded: [pos][k] (k=0..63, pad 64..67)
__device__ float g_MCr[384 * 32];       // row-major: rows 0-191 qS weights, 192-383 qX
__device__ float g_Pc[NN * 192];        // per-node constant (permuted-g) incl. bias fold
__device__ float g_Q[(size_t)NB * TT * 384];  // precomputed qS|qX per (b,t)

__device__ __forceinline__ float sigmf(float x) {
    return 1.0f / (1.0f + __expf(-x));
}
__device__ __forceinline__ float tanhfast(float x) {
    float e = __expf(-2.0f * x);
    return (1.0f - e) / (1.0f + e);
}

// permuted g position: [in 0:48 | out 0:48 | in 48:96 | out 48:96]
__device__ __forceinline__ int gpos(int gg, int is_out) {
    return (gg / 48) * 96 + (is_out ? 48 : 0) + (gg % 48);
}

// ---------------------------------------------------------------------------
// Setup launch 1: build CSC (zero-padded to CSCPAD)
// ---------------------------------------------------------------------------
__global__ void build_csc_kernel(const float* __restrict__ adj) {
    int v = blockIdx.x;
    int t = threadIdx.x;          // 256 threads, each handles 4 u's
    __shared__ int cnt[256];

    int base = t * 4;
    int flags = 0, c = 0;
    #pragma unroll
    for (int i = 0; i < 4; i++) {
        float a = adj[(base + i) * NN + v];
        if (a != 0.0f) { c++; flags |= (1 << i); }
    }
    cnt[t] = c;
    __syncthreads();
    for (int st = 1; st < 256; st <<= 1) {
        int val = cnt[t];
        int add = (t >= st) ? cnt[t - st] : 0;
        __syncthreads();
        cnt[t] = val + add;
        __syncthreads();
    }
    int off = cnt[t] - c;
    int total = cnt[255];
    int w = 0;
    #pragma unroll
    for (int i = 0; i < 4; i++) {
        if (flags & (1 << i)) {
            int idx = off + w;
            if (idx < MAXDEG) g_csc[v * CSCPAD + idx] = base + i;
            w++;
        }
    }
    int tot = (total < MAXDEG) ? total : MAXDEG;
    if (t == 0) g_deg[v] = tot;
    for (int p = tot + t; p < CSCPAD; p += 256) g_csc[v * CSCPAD + p] = 0;
}

// ---------------------------------------------------------------------------
// Setup launch 2 (merged): blocks 0-255 -> Cn (4 nodes each);
//                          blocks 256-447 -> M row (idx = blockIdx-256)
// ---------------------------------------------------------------------------
__global__ void setup2_kernel(const float* __restrict__ item_emb,
                              const float* __restrict__ w_ih,
                              const float* __restrict__ w_in,
                              const float* __restrict__ w_out) {
    if (blockIdx.x < 256) {
        // Cn[v][d] = sum over in-neighbors u of item_emb[u][d]
        int v = blockIdx.x * 4 + (threadIdx.x >> 5);
        int d = threadIdx.x & 31;
        int deg = g_deg[v];
        float s = 0.0f;
        for (int k = 0; k < deg; k++) {
            int u = g_csc[v * CSCPAD + k];
            s += item_emb[u * DD + d];
        }
        g_Cn[v * DD + d] = s;
    } else {
        int idx = blockIdx.x - 256;    // 0..191
        int k = threadIdx.x;           // 0..127
        int is_out = idx >= 96;
        int gg = idx % 96;
        int pos = gpos(gg, is_out);
        const float* wio = is_out ? w_out : w_in;
        float acc = 0.0f;
        #pragma unroll 8
        for (int o = 0; o < FF; o++) acc += w_ih[gg * FF + o] * wio[o * 128 + k];
        g_M[idx * 128 + k] = acc;
        // k-major padded layout for the GEMM: x = [h(0..31), agg(32..63)]
        if (k < 32)                 g_MXk[pos * 68 + k] = acc;            // h cols
        else if (k >= 64 && k < 96) g_MXk[pos * 68 + (k - 32)] = acc;     // agg cols
        else if (k >= 32 && k < 64) g_MCr[pos * 32 + (k - 32)] = acc;     // merged (qS)
        else                        g_MCr[(192 + pos) * 32 + (k - 96)] = acc; // Cn (qX)
        // zero the pad once per pos (k==0 thread)
        if (k == 0) {
            g_MXk[pos * 68 + 64] = 0.0f; g_MXk[pos * 68 + 65] = 0.0f;
            g_MXk[pos * 68 + 66] = 0.0f; g_MXk[pos * 68 + 67] = 0.0f;
        }
    }
}

// ---------------------------------------------------------------------------
// Setup launch 3 (merged): blocks 0-63 -> Pc (16 nodes each);
//   blocks 64-4159 -> Q table per (b,t); rest -> state init.
// ---------------------------------------------------------------------------
#define S3_PC_BLOCKS 64
#define S3_Q_BLOCKS  (NB * TT)
#define S3_INIT_BLOCKS ((GG * BN) / 384)
#define S3_GRID (S3_PC_BLOCKS + S3_Q_BLOCKS + S3_INIT_BLOCKS)

__global__ void __launch_bounds__(384) setup3_kernel(
    const int* __restrict__ item_ids, const int* __restrict__ responses,
    const float* __restrict__ item_emb, const float* __restrict__ resp_emb,
    const float* __restrict__ w_ih,
    const float* __restrict__ b_in, const float* __restrict__ b_out,
    const float* __restrict__ b_ih) {
    __shared__ float sbuf[16 * 32 * 2];   // Pc: ie|cn ; Q: sd (first 32)
    int bx = blockIdx.x;
    int tid = threadIdx.x;

    if (bx < S3_PC_BLOCKS) {
        float* ie = sbuf;            // [16][32]
        float* cn = sbuf + 512;      // [16][32]
        int v0 = bx * 16;
        for (int i = tid; i < 16 * 32; i += 384) {
            int vv = i >> 5, d = i & 31;
            ie[vv * 32 + d] = item_emb[(v0 + vv) * DD + d];
            cn[vv * 32 + d] = g_Cn[(v0 + vv) * DD + d];
        }
        __syncthreads();
        if (tid < 192) {
            int idx = tid;
            int is_out = idx >= 96;
            int gg = idx % 96;
            int pos = gpos(gg, is_out);
            float m1[32], m2[32];
            #pragma unroll
            for (int k = 0; k < 32; k++) {
                m1[k] = g_M[idx * 128 + 32 + k];
                m2[k] = g_M[idx * 128 + 96 + k];
            }
            const float* bio = is_out ? b_out : b_in;
            float wb = 0.0f;
            #pragma unroll 8
            for (int o = 0; o < FF; o++) wb += w_ih[gg * FF + o] * bio[o];
            for (int vv = 0; vv < 16; vv++) {
                float acc = wb;
                #pragma unroll
                for (int k = 0; k < 32; k++)
                    acc += m1[k] * ie[vv * 32 + k] + m2[k] * cn[vv * 32 + k];
                g_Pc[(v0 + vv) * 192 + pos] = acc;
            }
        }
    } else if (bx < S3_PC_BLOCKS + S3_Q_BLOCKS) {
        int idx2 = bx - S3_PC_BLOCKS;
        int t = idx2 % TT, b = idx2 / TT;
        float* sd = sbuf;
        if (tid < 32) {
            int item = item_ids[b * TT + t];
            int resp = responses[b * TT + t];
            sd[tid] = resp_emb[resp * DD + tid] - item_emb[item * DD + tid];
        }
        __syncthreads();
        const float4* row = reinterpret_cast<const float4*>(g_MCr + tid * 32);
        float acc = 0.0f;
        #pragma unroll
        for (int q = 0; q < 8; q++) {
            float4 wv = row[q];
            acc += wv.x * sd[q * 4 + 0] + wv.y * sd[q * 4 + 1]
                 + wv.z * sd[q * 4 + 2] + wv.w * sd[q * 4 + 3];
        }
        g_Q[((size_t)b * TT + t) * 384 + tid] = acc;
    } else {
        int i = (bx - S3_PC_BLOCKS - S3_Q_BLOCKS) * 384 + tid;
        g_Gi[i] = b_ih[i / BN];
        if (i < BN * SS) g_h[i] = 0.0f;
    }
}

// ---------------------------------------------------------------------------
// Kernel A6: sparse Gi refresh — gather phase + register-tiled 2-node GEMM.
// Grid (2, NB) x 512 threads. Block (half,b) handles nodes j = 2*jj + half.
// Shared layout (floats):
//   [0)      MXk   192*68 = 13056
//   [13056)  X     48*68  = 3264
//   [16320)  tb    16*192 = 3072
//   [19392)  qS 192 | qX 192 | bihs 96 | metaF 48*4 | metaV 48
// total 20112 floats = 80448 bytes
// ---------------------------------------------------------------------------
#define SP6_SMEM_FLOATS 20112
#define SP6_SMEM_BYTES  (SP6_SMEM_FLOATS * 4)

__device__ __forceinline__ void sp6_epilogue(
    const float acc[6], int n, int lane, int b,
    float* tb, const float* qS, const float* qX, const float* bihs,
    const float* metaF, const int* metaV)
{
    int v = metaV[n];
    float ia   = metaF[n * 4 + 0];
    float oa   = metaF[n * 4 + 1];
    bool  rev  = metaF[n * 4 + 2] != 0.0f;
    bool  self = metaF[n * 4 + 3] != 0.0f;
    #pragma unroll
    for (int m = 0; m < 6; m++) {
        int pos = lane + 32 * m;
        float a = acc[m] + g_Pc[v * 192 + pos];
        if (rev)  a += qX[pos];
        if (self) a += qS[pos];
        tb[pos] = a;
    }
    __syncwarp();
    #pragma unroll
    for (int m = 0; m < 3; m++) {
        int gg = lane + 32 * m;
        int q = (gg >= 48) ? 1 : 0;
        int pos_in = q * 96 + (gg - 48 * q);
        float gi = bihs[gg] + ia * tb[pos_in] + oa * tb[pos_in + 48];
        g_Gi[(size_t)gg * BN + b * NN + v] = gi;
    }
    __syncwarp();
}

__global__ void __launch_bounds__(512) step_sparse6(
    const int* __restrict__ item_ids, int t,
    const float* __restrict__ adj,
    const float* __restrict__ in_a, const float* __restrict__ out_a,
    const float* __restrict__ b_ih)
{
    extern __shared__ float smem[];
    float* MXk   = smem;                  // [192][68]
    float* X     = smem + 13056;          // [48][68]
    float* tbA   = smem + 16320;          // [16][192]
    float* qS    = smem + 19392;          // [192]
    float* qX    = smem + 19584;          // [192]
    float* bihs  = smem + 19776;          // [96]
    float* metaF = smem + 19872;          // [48][4]: ia, oa, rev, self
    int*   metaV = (int*)(smem + 20064);  // [48]

    int b = blockIdx.y, half = blockIdx.x;
    int tid = threadIdx.x, lane = tid & 31, w = tid >> 5;
    int item = item_ids[b * TT + t];
    int deg = g_deg[item];
    int ncount = (deg > half) ? ((deg - half + 1) >> 1) : 0;

    // ---- prologue: copy weights (float4 coalesced) + q + bias ----
    {
        const float4* src = reinterpret_cast<const float4*>(g_MXk);
        float4* dst = reinterpret_cast<float4*>(MXk);
        for (int i = tid; i < 3264; i += 512) dst[i] = src[i];
    }
    if (tid < 384) qS[tid] = g_Q[((size_t)b * TT + t) * 384 + tid];  // qS|qX contiguous
    if (tid >= 384 && tid < 480) bihs[tid - 384] = b_ih[tid - 384];

    // ---- phase 1: gather X rows + node meta (no barrier needed before) ----
    const float* hb = g_h + (size_t)b * NN * SS;
    for (int jj = w; jj < ncount; jj += 16) {
        int v = g_csc[item * CSCPAD + 2 * jj + half];
        int degv = g_deg[v];
        const int* nb = g_csc + v * CSCPAD;
        float acc0 = 0.0f, acc1 = 0.0f;
        for (int k = 0; k < degv; k += 16) {
            #pragma unroll
            for (int i = 0; i < 16; i += 2) {
                int u0 = nb[k + i];
                int u1 = nb[k + i + 1];
                float x0 = hb[u0 * SS + lane];
                float x1 = hb[u1 * SS + lane];
                if (k + i < degv)     acc0 += x0;
                if (k + i + 1 < degv) acc1 += x1;
            }
        }
        X[jj * 68 + lane]      = hb[v * SS + lane];
        X[jj * 68 + 32 + lane] = acc0 + acc1;
        if (lane == 0) { metaV[jj] = v; metaF[jj * 4 + 0] = in_a[v]; }
        if (lane == 1) metaF[jj * 4 + 1] = out_a[v];
        if (lane == 2) metaF[jj * 4 + 2] = adj[(size_t)item * NN + v];
        if (lane == 3) metaF[jj * 4 + 3] = (v == item) ? 1.0f : 0.0f;
    }
    __syncthreads();

    // ---- phase 2: T[192 x ncount] = MXk[192x64] @ X, 2 nodes per warp ----
    float* tb = tbA + w * 192;
    for (int p = w; 2 * p < ncount; p += 16) {
        int n0 = 2 * p, n1 = 2 * p + 1;
        bool has1 = n1 < ncount;
        float acc0[6] = {0, 0, 0, 0, 0, 0};
        float acc1[6] = {0, 0, 0, 0, 0, 0};
        const float4* x0 = reinterpret_cast<const float4*>(X + n0 * 68);
        const float4* x1 = reinterpret_cast<const float4*>(X + n1 * 68);
        #pragma unroll 4
        for (int k4 = 0; k4 < 16; k4++) {
            float4 a4 = x0[k4];
            float4 b4 = x1[k4];
            #pragma unroll
            for (int m = 0; m < 6; m++) {
                const float4 wv = *reinterpret_cast<const float4*>(
                    MXk + (lane + 32 * m) * 68 + k4 * 4);
                acc0[m] += wv.x * a4.x + wv.y * a4.y + wv.z * a4.z + wv.w * a4.w;
                acc1[m] += wv.x * b4.x + wv.y * b4.y + wv.z * b4.z + wv.w * b4.w;
            }
        }
        sp6_epilogue(acc0, n0, lane, b, tb, qS, qX, bihs, metaF, metaV);
        if (has1)
            sp6_epilogue(acc1, n1, lane, b, tb, qS, qX, bihs, metaF, metaV);
    }
}

// ---------------------------------------------------------------------------
// Kernel B5: GRU, one row per thread. Grid 128 x 512 — single balanced wave.
// ---------------------------------------------------------------------------
__global__ void __launch_bounds__(512) step_gru5(
    const float* __restrict__ w_hh, const float* __restrict__ b_hh,
    const float* __restrict__ w_fc, const float* __restrict__ b_fc,
    float* __restrict__ out, int t, float* __restrict__ h_final)
{
    __shared__ __align__(16) float whh[GG * SS];
    __shared__ float bhh[GG];
    __shared__ float wfc[SS];

    int tid = threadIdx.x;
    for (int i = tid; i < GG * SS; i += 512) whh[i] = w_hh[i];
    if (tid < GG) bhh[tid] = b_hh[tid];
    if (tid < SS) wfc[tid] = w_fc[tid];
    __syncthreads();

    const float4* whh4 = reinterpret_cast<const float4*>(whh);

    int r = blockIdx.x * 512 + tid;

    float h[SS];
    {
        const float4* hp = reinterpret_cast<const float4*>(g_h + (size_t)r * SS);
        #pragma unroll
        for (int q = 0; q < 8; q++) {
            float4 hv = hp[q];
            h[q * 4 + 0] = hv.x; h[q * 4 + 1] = hv.y;
            h[q * 4 + 2] = hv.z; h[q * 4 + 3] = hv.w;
        }
    }

    float4* hrow  = reinterpret_cast<float4*>(g_h + (size_t)r * SS);
    float4* hfrow = h_final ? reinterpret_cast<float4*>(h_final + (size_t)r * SS)
                            : nullptr;

    float fc = 0.0f;
    float o0, o1, o2, o3;

    #pragma unroll
    for (int d = 0; d < SS; d++) {
        float ar = bhh[d], az = bhh[SS + d], an = bhh[2 * SS + d];
        #pragma unroll
        for (int q = 0; q < 8; q++) {
            float4 wr = whh4[(d * SS) / 4 + q];
            float4 wz = whh4[((SS + d) * SS) / 4 + q];
            float4 wn = whh4[((2 * SS + d) * SS) / 4 + q];
            float h0 = h[q * 4 + 0], h1 = h[q * 4 + 1];
            float h2 = h[q * 4 + 2], h3 = h[q * 4 + 3];
            ar += wr.x * h0 + wr.y * h1 + wr.z * h2 + wr.w * h3;
            az += wz.x * h0 + wz.y * h1 + wz.z * h2 + wz.w * h3;
            an += wn.x * h0 + wn.y * h1 + wn.z * h2 + wn.w * h3;
        }
        float gr = g_Gi[(size_t)d * BN + r];
        float gz = g_Gi[(size_t)(SS + d) * BN + r];
        float gn = g_Gi[(size_t)(2 * SS + d) * BN + r];
        float rr = sigmf(ar + gr);
        float zz = sigmf(az + gz);
        float nn = tanhfast(gn + rr * an);
        float hn = (1.0f - zz) * nn + zz * h[d];
        fc += hn * wfc[d];
        if ((d & 3) == 0) o0 = hn;
        else if ((d & 3) == 1) o1 = hn;
        else if ((d & 3) == 2) o2 = hn;
        else {
            o3 = hn;
            float4 ov; ov.x = o0; ov.y = o1; ov.z = o2; ov.w = o3;
            hrow[d / 4] = ov;
            if (hfrow) hfrow[d / 4] = ov;
        }
    }

    int b0 = r >> 10;
    int v0 = r & (NN - 1);
    out[((size_t)b0 * TT + t) * NN + v0] = sigmf(fc + b_fc[0]);
}

// ---------------------------------------------------------------------------
extern "C" void kernel_launch(void* const* d_in, const int* in_sizes, int n_in,
                              void* d_out, int out_size) {
    const int*   item_ids  = (const int*)  d_in[0];
    const int*   responses = (const int*)  d_in[1];
    const float* adj       = (const float*)d_in[2];
    const float* item_emb  = (const float*)d_in[3];
    const float* resp_emb  = (const float*)d_in[4];
    const float* w_in      = (const float*)d_in[5];
    const float* b_in      = (const float*)d_in[6];
    const float* w_out     = (const float*)d_in[7];
    const float* b_out     = (const float*)d_in[8];
    const float* in_a      = (const float*)d_in[9];
    const float* out_a     = (const float*)d_in[10];
    const float* w_ih      = (const float*)d_in[11];
    const float* w_hh      = (const float*)d_in[12];
    const float* b_ih      = (const float*)d_in[13];
    const float* b_hh      = (const float*)d_in[14];
    const float* w_fc      = (const float*)d_in[15];
    const float* b_fc      = (const float*)d_in[16];

    float* out    = (float*)d_out;                       // (B, T, N)
    float* h_out  = out + (size_t)NB * TT * NN;          // (B, N, S)

    cudaFuncSetAttribute(step_sparse6,
                         cudaFuncAttributeMaxDynamicSharedMemorySize,
                         SP6_SMEM_BYTES);

    build_csc_kernel<<<NN, 256>>>(adj);
    setup2_kernel<<<448, 128>>>(item_emb, w_ih, w_in, w_out);
    setup3_kernel<<<S3_GRID, 384>>>(item_ids, responses, item_emb, resp_emb,
                                    w_ih, b_in, b_out, b_ih);

    for (int t = 0; t < TT; t++) {
        step_sparse6<<<dim3(2, NB), 512, SP6_SMEM_BYTES>>>(
            item_ids, t, adj, in_a, out_a, b_ih);
        step_gru5<<<BN / 512, 512>>>(
            w_hh, b_hh, w_fc, b_fc, out, t,
            (t == TT - 1) ? h_out : nullptr);
    }
}

// round 17
// speedup vs baseline: 1.3358x; 1.0019x over previous
#include <cuda_runtime.h>
#include <cuda_bf16.h>
#include <cstdint>

#define NB   64      // batch
#define TT   64      // seq len
#define NN   1024    // items
#define SS   32      // state dim
#define DD   32      // item dim
#define FF   64      // feature = SS + DD
#define GG   96      // 3 * SS
#define MAXDEG 96
#define CSCPAD 112   // padded stride so unroll-16 gather never reads OOB
#define BN   (NB * NN)

// Persistent state (module globals — no runtime allocation)
__device__ float g_h[BN * SS];          // (row, s) row-major
__device__ float g_Gi[GG * BN];         // TRANSPOSED: (g, row)
__device__ int   g_csc[NN * CSCPAD];    // in-neighbors of each v (zero-padded)
__device__ int   g_deg[NN];
__device__ float g_Cn[NN * DD];         // adj^T @ item_emb
// Folded weights
__device__ float g_M[192 * 128];        // [w_ih@w_in ; w_ih@w_out], original order
__device__ float g_MXk[192 * 68];       // k-major padded: [pos][k] (k=0..63, pad 64..67)
__device__ float g_MCr[384 * 32];       // row-major: rows 0-191 qS weights, 192-383 qX
__device__ float g_Pc[NN * 192];        // per-node constant (permuted-g) incl. bias fold
__device__ float g_Q[(size_t)NB * TT * 384];  // precomputed qS|qX per (b,t)

__device__ __forceinline__ float sigmf(float x) {
    return 1.0f / (1.0f + __expf(-x));
}
__device__ __forceinline__ float tanhfast(float x) {
    float e = __expf(-2.0f * x);
    return (1.0f - e) / (1.0f + e);
}
__device__ __forceinline__ unsigned long long pack2(float lo, float hi) {
    unsigned long long r;
    asm("mov.b64 %0, {%1, %2};" : "=l"(r) : "f"(lo), "f"(hi));
    return r;
}
__device__ __forceinline__ void unpack2(unsigned long long v, float& lo, float& hi) {
    asm("mov.b64 {%0, %1}, %2;" : "=f"(lo), "=f"(hi) : "l"(v));
}
__device__ __forceinline__ unsigned long long ffma2(unsigned long long a,
                                                    unsigned long long b,
                                                    unsigned long long c) {
    unsigned long long d;
    asm("fma.rn.f32x2 %0, %1, %2, %3;" : "=l"(d) : "l"(a), "l"(b), "l"(c));
    return d;
}

// permuted g position: [in 0:48 | out 0:48 | in 48:96 | out 48:96]
__device__ __forceinline__ int gpos(int gg, int is_out) {
    return (gg / 48) * 96 + (is_out ? 48 : 0) + (gg % 48);
}

// ---------------------------------------------------------------------------
// Setup launch 1: build CSC (zero-padded to CSCPAD)
// ---------------------------------------------------------------------------
__global__ void build_csc_kernel(const float* __restrict__ adj) {
    int v = blockIdx.x;
    int t = threadIdx.x;          // 256 threads, each handles 4 u's
    __shared__ int cnt[256];

    int base = t * 4;
    int flags = 0, c = 0;
    #pragma unroll
    for (int i = 0; i < 4; i++) {
        float a = adj[(base + i) * NN + v];
        if (a != 0.0f) { c++; flags |= (1 << i); }
    }
    cnt[t] = c;
    __syncthreads();
    for (int st = 1; st < 256; st <<= 1) {
        int val = cnt[t];
        int add = (t >= st) ? cnt[t - st] : 0;
        __syncthreads();
        cnt[t] = val + add;
        __syncthreads();
    }
    int off = cnt[t] - c;
    int total = cnt[255];
    int w = 0;
    #pragma unroll
    for (int i = 0; i < 4; i++) {
        if (flags & (1 << i)) {
            int idx = off + w;
            if (idx < MAXDEG) g_csc[v * CSCPAD + idx] = base + i;
            w++;
        }
    }
    int tot = (total < MAXDEG) ? total : MAXDEG;
    if (t == 0) g_deg[v] = tot;
    for (int p = tot + t; p < CSCPAD; p += 256) g_csc[v * CSCPAD + p] = 0;
}

// ---------------------------------------------------------------------------
// Setup launch 2 (merged): blocks 0-255 -> Cn (4 nodes each);
//                          blocks 256-447 -> M row (idx = blockIdx-256)
// ---------------------------------------------------------------------------
__global__ void setup2_kernel(const float* __restrict__ item_emb,
                              const float* __restrict__ w_ih,
                              const float* __restrict__ w_in,
                              const float* __restrict__ w_out) {
    if (blockIdx.x < 256) {
        int v = blockIdx.x * 4 + (threadIdx.x >> 5);
        int d = threadIdx.x & 31;
        int deg = g_deg[v];
        float s = 0.0f;
        for (int k = 0; k < deg; k++) {
            int u = g_csc[v * CSCPAD + k];
            s += item_emb[u * DD + d];
        }
        g_Cn[v * DD + d] = s;
    } else {
        int idx = blockIdx.x - 256;    // 0..191
        int k = threadIdx.x;           // 0..127
        int is_out = idx >= 96;
        int gg = idx % 96;
        int pos = gpos(gg, is_out);
        const float* wio = is_out ? w_out : w_in;
        float acc = 0.0f;
        #pragma unroll 8
        for (int o = 0; o < FF; o++) acc += w_ih[gg * FF + o] * wio[o * 128 + k];
        g_M[idx * 128 + k] = acc;
        if (k < 32)                 g_MXk[pos * 68 + k] = acc;            // h cols
        else if (k >= 64 && k < 96) g_MXk[pos * 68 + (k - 32)] = acc;     // agg cols
        else if (k >= 32 && k < 64) g_MCr[pos * 32 + (k - 32)] = acc;     // merged (qS)
        else                        g_MCr[(192 + pos) * 32 + (k - 96)] = acc; // Cn (qX)
        if (k == 0) {
            g_MXk[pos * 68 + 64] = 0.0f; g_MXk[pos * 68 + 65] = 0.0f;
            g_MXk[pos * 68 + 66] = 0.0f; g_MXk[pos * 68 + 67] = 0.0f;
        }
    }
}

// ---------------------------------------------------------------------------
// Setup launch 3 (merged): blocks 0-63 -> Pc (16 nodes each);
//   blocks 64-4159 -> Q table per (b,t); rest -> state init.
// ---------------------------------------------------------------------------
#define S3_PC_BLOCKS 64
#define S3_Q_BLOCKS  (NB * TT)
#define S3_INIT_BLOCKS ((GG * BN) / 384)
#define S3_GRID (S3_PC_BLOCKS + S3_Q_BLOCKS + S3_INIT_BLOCKS)

__global__ void __launch_bounds__(384) setup3_kernel(
    const int* __restrict__ item_ids, const int* __restrict__ responses,
    const float* __restrict__ item_emb, const float* __restrict__ resp_emb,
    const float* __restrict__ w_ih,
    const float* __restrict__ b_in, const float* __restrict__ b_out,
    const float* __restrict__ b_ih) {
    __shared__ float sbuf[16 * 32 * 2];   // Pc: ie|cn ; Q: sd (first 32)
    int bx = blockIdx.x;
    int tid = threadIdx.x;

    if (bx < S3_PC_BLOCKS) {
        float* ie = sbuf;            // [16][32]
        float* cn = sbuf + 512;      // [16][32]
        int v0 = bx * 16;
        for (int i = tid; i < 16 * 32; i += 384) {
            int vv = i >> 5, d = i & 31;
            ie[vv * 32 + d] = item_emb[(v0 + vv) * DD + d];
            cn[vv * 32 + d] = g_Cn[(v0 + vv) * DD + d];
        }
        __syncthreads();
        if (tid < 192) {
            int idx = tid;
            int is_out = idx >= 96;
            int gg = idx % 96;
            int pos = gpos(gg, is_out);
            float m1[32], m2[32];
            #pragma unroll
            for (int k = 0; k < 32; k++) {
                m1[k] = g_M[idx * 128 + 32 + k];
                m2[k] = g_M[idx * 128 + 96 + k];
            }
            const float* bio = is_out ? b_out : b_in;
            float wb = 0.0f;
            #pragma unroll 8
            for (int o = 0; o < FF; o++) wb += w_ih[gg * FF + o] * bio[o];
            for (int vv = 0; vv < 16; vv++) {
                float acc = wb;
                #pragma unroll
                for (int k = 0; k < 32; k++)
                    acc += m1[k] * ie[vv * 32 + k] + m2[k] * cn[vv * 32 + k];
                g_Pc[(v0 + vv) * 192 + pos] = acc;
            }
        }
    } else if (bx < S3_PC_BLOCKS + S3_Q_BLOCKS) {
        int idx2 = bx - S3_PC_BLOCKS;
        int t = idx2 % TT, b = idx2 / TT;
        float* sd = sbuf;
        if (tid < 32) {
            int item = item_ids[b * TT + t];
            int resp = responses[b * TT + t];
            sd[tid] = resp_emb[resp * DD + tid] - item_emb[item * DD + tid];
        }
        __syncthreads();
        const float4* row = reinterpret_cast<const float4*>(g_MCr + tid * 32);
        float acc = 0.0f;
        #pragma unroll
        for (int q = 0; q < 8; q++) {
            float4 wv = row[q];
            acc += wv.x * sd[q * 4 + 0] + wv.y * sd[q * 4 + 1]
                 + wv.z * sd[q * 4 + 2] + wv.w * sd[q * 4 + 3];
        }
        g_Q[((size_t)b * TT + t) * 384 + tid] = acc;
    } else {
        int i = (bx - S3_PC_BLOCKS - S3_Q_BLOCKS) * 384 + tid;
        g_Gi[i] = b_ih[i / BN];
        if (i < BN * SS) g_h[i] = 0.0f;
    }
}

// ---------------------------------------------------------------------------
// Kernel A7: sparse Gi refresh — 4-way node split, 256-thread blocks,
// ~67KB smem -> 3 blocks/SM co-residency for latency hiding.
// Grid (4, NB). Block (quarter, b) handles nodes j = 4*jj + quarter.
// Shared layout (floats):
//   [0)      MXk   192*68 = 13056
//   [13056)  X     24*68  = 1632
//   [14688)  tb    8*192  = 1536
//   [16224)  qS 192 | qX 192 | bihs 96 | metaF 24*4 | metaV 24
// total 16824 floats = 67296 bytes
// ---------------------------------------------------------------------------
#define SP7_SMEM_FLOATS 16824
#define SP7_SMEM_BYTES  (SP7_SMEM_FLOATS * 4)

__device__ __forceinline__ void sp7_epilogue(
    const float acc[6], int n, int lane, int b,
    float* tb, const float* qS, const float* qX, const float* bihs,
    const float* metaF, const int* metaV)
{
    int v = metaV[n];
    float ia   = metaF[n * 4 + 0];
    float oa   = metaF[n * 4 + 1];
    bool  rev  = metaF[n * 4 + 2] != 0.0f;
    bool  self = metaF[n * 4 + 3] != 0.0f;
    #pragma unroll
    for (int m = 0; m < 6; m++) {
        int pos = lane + 32 * m;
        float a = acc[m] + g_Pc[v * 192 + pos];
        if (rev)  a += qX[pos];
        if (self) a += qS[pos];
        tb[pos] = a;
    }
    __syncwarp();
    #pragma unroll
    for (int m = 0; m < 3; m++) {
        int gg = lane + 32 * m;
        int q = (gg >= 48) ? 1 : 0;
        int pos_in = q * 96 + (gg - 48 * q);
        float gi = bihs[gg] + ia * tb[pos_in] + oa * tb[pos_in + 48];
        g_Gi[(size_t)gg * BN + b * NN + v] = gi;
    }
    __syncwarp();
}

__global__ void __launch_bounds__(256) step_sparse7(
    const int* __restrict__ item_ids, int t,
    const float* __restrict__ adj,
    const float* __restrict__ in_a, const float* __restrict__ out_a,
    const float* __restrict__ b_ih)
{
    extern __shared__ float smem[];
    float* MXk   = smem;                  // [192][68]
    float* X     = smem + 13056;          // [24][68]
    float* tbA   = smem + 14688;          // [8][192]
    float* qS    = smem + 16224;          // [192]
    float* qX    = smem + 16416;          // [192]
    float* bihs  = smem + 16608;          // [96]
    float* metaF = smem + 16704;          // [24][4]: ia, oa, rev, self
    int*   metaV = (int*)(smem + 16800);  // [24]

    int b = blockIdx.y, quarter = blockIdx.x;
    int tid = threadIdx.x, lane = tid & 31, w = tid >> 5;
    int item = item_ids[b * TT + t];
    int deg = g_deg[item];
    int ncount = (deg > quarter) ? ((deg - quarter + 3) >> 2) : 0;

    // ---- prologue: copy weights (float4 coalesced) + q + bias ----
    {
        const float4* src = reinterpret_cast<const float4*>(g_MXk);
        float4* dst = reinterpret_cast<float4*>(MXk);
        for (int i = tid; i < 3264; i += 256) dst[i] = src[i];
    }
    for (int i = tid; i < 384; i += 256) qS[i] = g_Q[((size_t)b * TT + t) * 384 + i];
    if (tid < 96) bihs[tid] = b_ih[tid];

    // ---- phase 1: gather X rows + node meta ----
    const float* hb = g_h + (size_t)b * NN * SS;
    for (int jj = w; jj < ncount; jj += 8) {
        int v = g_csc[item * CSCPAD + 4 * jj + quarter];
        int degv = g_deg[v];
        const int* nb = g_csc + v * CSCPAD;
        float acc0 = 0.0f, acc1 = 0.0f;
        for (int k = 0; k < degv; k += 16) {
            #pragma unroll
            for (int i = 0; i < 16; i += 2) {
                int u0 = nb[k + i];
                int u1 = nb[k + i + 1];
                float x0 = hb[u0 * SS + lane];
                float x1 = hb[u1 * SS + lane];
                if (k + i < degv)     acc0 += x0;
                if (k + i + 1 < degv) acc1 += x1;
            }
        }
        X[jj * 68 + lane]      = hb[v * SS + lane];
        X[jj * 68 + 32 + lane] = acc0 + acc1;
        if (lane == 0) { metaV[jj] = v; metaF[jj * 4 + 0] = in_a[v]; }
        if (lane == 1) metaF[jj * 4 + 1] = out_a[v];
        if (lane == 2) metaF[jj * 4 + 2] = adj[(size_t)item * NN + v];
        if (lane == 3) metaF[jj * 4 + 3] = (v == item) ? 1.0f : 0.0f;
    }
    __syncthreads();

    // ---- phase 2: T[192 x ncount] = MXk[192x64] @ X, 2 nodes per warp ----
    float* tb = tbA + w * 192;
    for (int p = w; 2 * p < ncount; p += 8) {
        int n0 = 2 * p, n1 = 2 * p + 1;
        bool has1 = n1 < ncount;
        float acc0[6] = {0, 0, 0, 0, 0, 0};
        float acc1[6] = {0, 0, 0, 0, 0, 0};
        const float4* x0 = reinterpret_cast<const float4*>(X + n0 * 68);
        const float4* x1 = reinterpret_cast<const float4*>(X + n1 * 68);
        #pragma unroll 4
        for (int k4 = 0; k4 < 16; k4++) {
            float4 a4 = x0[k4];
            float4 b4 = x1[k4];
            #pragma unroll
            for (int m = 0; m < 6; m++) {
                const float4 wv = *reinterpret_cast<const float4*>(
                    MXk + (lane + 32 * m) * 68 + k4 * 4);
                acc0[m] += wv.x * a4.x + wv.y * a4.y + wv.z * a4.z + wv.w * a4.w;
                acc1[m] += wv.x * b4.x + wv.y * b4.y + wv.z * b4.z + wv.w * b4.w;
            }
        }
        sp7_epilogue(acc0, n0, lane, b, tb, qS, qX, bihs, metaF, metaV);
        if (has1)
            sp7_epilogue(acc1, n1, lane, b, tb, qS, qX, bihs, metaF, metaV);
    }
}

// ---------------------------------------------------------------------------
// Kernel B6: GRU with f32x2 within-row packing. One row per thread.
// Grid 128 x 512. w_hh rows reinterpreted as u64 k-pairs (no repack needed).
// ---------------------------------------------------------------------------
__global__ void __launch_bounds__(512) step_gru6(
    const float* __restrict__ w_hh, const float* __restrict__ b_hh,
    const float* __restrict__ w_fc, const float* __restrict__ b_fc,
    float* __restrict__ out, int t, float* __restrict__ h_final)
{
    __shared__ __align__(16) float whh[GG * SS];
    __shared__ float bhh[GG];
    __shared__ float wfc[SS];

    int tid = threadIdx.x;
    for (int i = tid; i < GG * SS; i += 512) whh[i] = w_hh[i];
    if (tid < GG) bhh[tid] = b_hh[tid];
    if (tid < SS) wfc[tid] = w_fc[tid];
    __syncthreads();

    // each row = 32 floats = 16 u64 pairs = 8 ulonglong2
    const ulonglong2* whhv = reinterpret_cast<const ulonglong2*>(whh);

    int r = blockIdx.x * 512 + tid;

    // load h row, pack adjacent pairs: h2[k] = {h[2k], h[2k+1]}
    unsigned long long h2[16];
    float hval[SS];
    {
        const float4* hp = reinterpret_cast<const float4*>(g_h + (size_t)r * SS);
        #pragma unroll
        for (int q = 0; q < 8; q++) {
            float4 hv = hp[q];
            hval[q * 4 + 0] = hv.x; hval[q * 4 + 1] = hv.y;
            hval[q * 4 + 2] = hv.z; hval[q * 4 + 3] = hv.w;
            h2[q * 2 + 0] = pack2(hv.x, hv.y);
            h2[q * 2 + 1] = pack2(hv.z, hv.w);
        }
    }

    float4* hrow  = reinterpret_cast<float4*>(g_h + (size_t)r * SS);
    float4* hfrow = h_final ? reinterpret_cast<float4*>(h_final + (size_t)r * SS)
                            : nullptr;

    float fc = 0.0f;
    float o0, o1, o2, o3;

    #pragma unroll
    for (int d = 0; d < SS; d++) {
        unsigned long long ar2 = 0ull, az2 = 0ull, an2 = 0ull;
        #pragma unroll
        for (int q = 0; q < 8; q++) {
            // row base (in ulonglong2 units): gate_row * 8 + q
            ulonglong2 wr = whhv[d * 8 + q];
            ulonglong2 wz = whhv[(SS + d) * 8 + q];
            ulonglong2 wn = whhv[(2 * SS + d) * 8 + q];
            unsigned long long ha = h2[q * 2 + 0];
            unsigned long long hb2 = h2[q * 2 + 1];
            ar2 = ffma2(wr.x, ha, ar2);
            az2 = ffma2(wz.x, ha, az2);
            an2 = ffma2(wn.x, ha, an2);
            ar2 = ffma2(wr.y, hb2, ar2);
            az2 = ffma2(wz.y, hb2, az2);
            an2 = ffma2(wn.y, hb2, an2);
        }
        float arl, arh, azl, azh, anl, anh;
        unpack2(ar2, arl, arh);
        unpack2(az2, azl, azh);
        unpack2(an2, anl, anh);
        float ar = arl + arh + bhh[d];
        float az = azl + azh + bhh[SS + d];
        float an = anl + anh + bhh[2 * SS + d];

        float gr = g_Gi[(size_t)d * BN + r];
        float gz = g_Gi[(size_t)(SS + d) * BN + r];
        float gn = g_Gi[(size_t)(2 * SS + d) * BN + r];
        float rr = sigmf(ar + gr);
        float zz = sigmf(az + gz);
        float nn = tanhfast(gn + rr * an);
        float hn = (1.0f - zz) * nn + zz * hval[d];
        fc += hn * wfc[d];
        if ((d & 3) == 0) o0 = hn;
        else if ((d & 3) == 1) o1 = hn;
        else if ((d & 3) == 2) o2 = hn;
        else {
            o3 = hn;
            float4 ov; ov.x = o0; ov.y = o1; ov.z = o2; ov.w = o3;
            hrow[d / 4] = ov;
            if (hfrow) hfrow[d / 4] = ov;
        }
    }

    int b0 = r >> 10;
    int v0 = r & (NN - 1);
    out[((size_t)b0 * TT + t) * NN + v0] = sigmf(fc + b_fc[0]);
}

// ---------------------------------------------------------------------------
extern "C" void kernel_launch(void* const* d_in, const int* in_sizes, int n_in,
                              void* d_out, int out_size) {
    const int*   item_ids  = (const int*)  d_in[0];
    const int*   responses = (const int*)  d_in[1];
    const float* adj       = (const float*)d_in[2];
    const float* item_emb  = (const float*)d_in[3];
    const float* resp_emb  = (const float*)d_in[4];
    const float* w_in      = (const float*)d_in[5];
    const float* b_in      = (const float*)d_in[6];
    const float* w_out     = (const float*)d_in[7];
    const float* b_out     = (const float*)d_in[8];
    const float* in_a      = (const float*)d_in[9];
    const float* out_a     = (const float*)d_in[10];
    const float* w_ih      = (const float*)d_in[11];
    const float* w_hh      = (const float*)d_in[12];
    const float* b_ih      = (const float*)d_in[13];
    const float* b_hh      = (const float*)d_in[14];
    const float* w_fc      = (const float*)d_in[15];
    const float* b_fc      = (const float*)d_in[16];

    float* out    = (float*)d_out;                       // (B, T, N)
    float* h_out  = out + (size_t)NB * TT * NN;          // (B, N, S)

    cudaFuncSetAttribute(step_sparse7,
                         cudaFuncAttributeMaxDynamicSharedMemorySize,
                         SP7_SMEM_BYTES);

    build_csc_kernel<<<NN, 256>>>(adj);
    setup2_kernel<<<448, 128>>>(item_emb, w_ih, w_in, w_out);
    setup3_kernel<<<S3_GRID, 384>>>(item_ids, responses, item_emb, resp_emb,
                                    w_ih, b_in, b_out, b_ih);

    for (int t = 0; t < TT; t++) {
        step_sparse7<<<dim3(4, NB), 256, SP7_SMEM_BYTES>>>(
            item_ids, t, adj, in_a, out_a, b_ih);
        step_gru6<<<BN / 512, 512>>>(
            w_hh, b_hh, w_fc, b_fc, out, t,
            (t == TT - 1) ? h_out : nullptr);
    }
}